// round 14
// baseline (speedup 1.0000x reference)
#include <cuda_runtime.h>
#include <cuda_bf16.h>
#include <cstdint>

#define PW 50
#define NPIX 2500            // 50*50 padded pixel rows per (b,u,v)
#define PLANE 2304           // 48*48
#define CH_STR 112896        // 7*7*2304
#define RPB 256              // pixel rows per block (4 warps x 64)
#define MARG 64
#define SA_ROWS 384          // MARG + RPB + MARG
#define NTHREADS 128

#define GP_HALF 40000        // one plane (2500 rows x 16B)
#define GP_PER  80000        // hi + lo per (b,uv)
#define STG_LO  6144         // lo plane offset within one stage buffer (384*16)
#define STG_BUF 12288        // one stage buffer (hi+lo)

// precomputed transposed planes: [b][uv][ hi 2500x16B | lo 2500x16B ]
__device__ __align__(16) unsigned char gPlane[2 * 49 * GP_PER];   // 7.84 MB

__device__ __forceinline__ uint32_t cvt2(float lo, float hi) {   // {lo16,hi16}
    uint32_t r;
    asm("cvt.rn.bf16x2.f32 %0, %1, %2;" : "=r"(r) : "f"(hi), "f"(lo));
    return r;
}
__device__ __forceinline__ void ldm4(uint32_t& r0, uint32_t& r1, uint32_t& r2,
                                     uint32_t& r3, uint32_t a) {
    asm volatile("ldmatrix.sync.aligned.m8n8.x4.shared.b16 {%0,%1,%2,%3}, [%4];"
                 : "=r"(r0), "=r"(r1), "=r"(r2), "=r"(r3) : "r"(a));
}
__device__ __forceinline__ void mma16816(float* c, uint32_t a0, uint32_t a1,
                                         uint32_t a2, uint32_t a3,
                                         uint32_t b0, uint32_t b1) {
    asm volatile(
        "mma.sync.aligned.m16n8k16.row.col.f32.bf16.bf16.f32 "
        "{%0,%1,%2,%3}, {%4,%5,%6,%7}, {%8,%9}, {%0,%1,%2,%3};"
        : "+f"(c[0]), "+f"(c[1]), "+f"(c[2]), "+f"(c[3])
        : "r"(a0), "r"(a1), "r"(a2), "r"(a3), "r"(b0), "r"(b1));
}
__device__ __forceinline__ void mma1688(float* c, uint32_t a0, uint32_t a1,
                                        uint32_t b0) {
    asm volatile(
        "mma.sync.aligned.m16n8k8.row.col.f32.bf16.bf16.f32 "
        "{%0,%1,%2,%3}, {%4,%5}, {%6}, {%0,%1,%2,%3};"
        : "+f"(c[0]), "+f"(c[1]), "+f"(c[2]), "+f"(c[3])
        : "r"(a0), "r"(a1), "r"(b0));
}

// ---- kernel 1: build padded hi/lo bf16 planes ----
__global__ __launch_bounds__(256) void conv4d_prep(const float* __restrict__ x)
{
    const int idx = blockIdx.x * 256 + threadIdx.x;
    if (idx >= 2 * 49 * NPIX) return;
    const int m    = idx % NPIX;
    const int rest = idx / NPIX;
    const int uvn  = rest % 49;
    const int b    = rest / 49;
    const int hp = m / PW, wp = m - hp * PW;

    uint32_t hi[4] = {0u, 0u, 0u, 0u};
    uint32_t lo[4] = {0u, 0u, 0u, 0u};
    if (hp >= 1 && hp <= 48 && wp >= 1 && wp <= 48) {
        const float* s = x + ((size_t)(b * 8) * 49 + uvn) * PLANE
                           + (hp - 1) * 48 + (wp - 1);
        float vch[8];
        #pragma unroll
        for (int c = 0; c < 8; c++) vch[c] = __ldg(s + c * CH_STR);
        #pragma unroll
        for (int q = 0; q < 4; q++) {
            hi[q] = cvt2(vch[2 * q], vch[2 * q + 1]);
            const float hf0 = __uint_as_float(hi[q] << 16);
            const float hf1 = __uint_as_float(hi[q] & 0xFFFF0000u);
            lo[q] = cvt2(vch[2 * q] - hf0, vch[2 * q + 1] - hf1);
        }
    }
    unsigned char* base = gPlane + (size_t)(b * 49 + uvn) * GP_PER + m * 16;
    *(uint4*)base             = make_uint4(hi[0], hi[1], hi[2], hi[3]);
    *(uint4*)(base + GP_HALF) = make_uint4(lo[0], lo[1], lo[2], lo[3]);
}

// ---- kernel 2: MMA mainloop with cp.async staging ----
__global__ __launch_bounds__(NTHREADS, 5) void conv4d_mma(
    const float* __restrict__ conv,
    const float* __restrict__ bias,
    float* __restrict__ out)
{
    __shared__ uint2 sBF[81 * 32];                                  // 20736 B
    __shared__ __align__(16) unsigned char sStage[2 * STG_BUF];     // 24576 B

    const int tid  = threadIdx.x;
    const int wid  = tid >> 5;
    const int lane = tid & 31;
    const int R0   = blockIdx.x * RPB;
    const int uv   = blockIdx.y;
    const int u    = uv / 7, v = uv % 7;
    const int b    = blockIdx.z;

    const uint32_t sStg = (uint32_t)__cvta_generic_to_shared(sStage);

    // B fragments: sBF[tap*32+ln] = {Whi pair, Wlo pair}
    for (int e = tid; e < 81 * 32; e += NTHREADS) {
        const int tap = e >> 5, ln = e & 31;
        const int o = ln >> 2, c0 = (ln & 3) * 2;
        const float w0 = conv[o * 648 + tap * 8 + c0];
        const float w1 = conv[o * 648 + tap * 8 + c0 + 1];
        const uint32_t hi01 = cvt2(w0, w1);
        const float hf0 = __uint_as_float(hi01 << 16);
        const float hf1 = __uint_as_float(hi01 & 0xFFFF0000u);
        sBF[e] = make_uint2(hi01, cvt2(w0 - hf0, w1 - hf1));
    }

    // valid (i0,i1) phases -> gmem plane base offsets
    size_t ph_gb[9];
    int ph_tap[9], nph = 0;
    #pragma unroll
    for (int i0 = 0; i0 < 3; i0++) {
        const int uu = u + i0 - 1;
        if (uu < 0 || uu >= 7) continue;
        #pragma unroll
        for (int i1 = 0; i1 < 3; i1++) {
            const int vv = v + i1 - 1;
            if (vv < 0 || vv >= 7) continue;
            ph_gb[nph]  = (size_t)(b * 49 + uu * 7 + vv) * GP_PER;
            ph_tap[nph] = (i0 * 3 + i1) * 9;
            nph++;
        }
    }

    // per-thread cp.async slots: 3 rows x (hi,lo); phase-independent addressing
    uint32_t st_dst[3]; int st_moff[3]; int st_sz[3];
    #pragma unroll
    for (int k = 0; k < 3; k++) {
        const int j = tid + k * NTHREADS;   // 0..383
        const int m = R0 - MARG + j;
        const bool ok = (m >= 0) && (m < NPIX);
        const int mc = ok ? m : 0;
        st_dst[k]  = sStg + j * 16;
        st_moff[k] = mc * 16;
        st_sz[k]   = ok ? 16 : 0;
    }

    // per-warp ldmatrix base addresses (within buffer 0)
    const int lnrow = lane & 15;
    const uint32_t plane_off = (lane < 16) ? 0u : (uint32_t)STG_LO;
    uint32_t abase[4];
    #pragma unroll
    for (int t = 0; t < 4; t++)
        abase[t] = sStg + plane_off + (MARG + wid * 64 + t * 16 + lnrow) * 16;

    float acc[4][4];
    #pragma unroll
    for (int t = 0; t < 4; t++)
        #pragma unroll
        for (int i = 0; i < 4; i++) acc[t][i] = 0.0f;

    // prologue: stage phase 0 into buffer 0
    {
        const unsigned char* src = gPlane + ph_gb[0];
        #pragma unroll
        for (int k = 0; k < 3; k++) {
            asm volatile("cp.async.ca.shared.global [%0], [%1], 16, %2;"
                         :: "r"(st_dst[k]), "l"(src + st_moff[k]), "r"(st_sz[k]));
            asm volatile("cp.async.ca.shared.global [%0], [%1], 16, %2;"
                         :: "r"(st_dst[k] + STG_LO),
                            "l"(src + GP_HALF + st_moff[k]), "r"(st_sz[k]));
        }
        asm volatile("cp.async.commit_group;");
    }

    for (int p = 0; p < nph; p++) {
        const bool pre = (p + 1 < nph);
        if (pre) {
            const uint32_t boff = (uint32_t)((p + 1) & 1) * STG_BUF;
            const unsigned char* src = gPlane + ph_gb[p + 1];
            #pragma unroll
            for (int k = 0; k < 3; k++) {
                asm volatile("cp.async.ca.shared.global [%0], [%1], 16, %2;"
                             :: "r"(st_dst[k] + boff), "l"(src + st_moff[k]), "r"(st_sz[k]));
                asm volatile("cp.async.ca.shared.global [%0], [%1], 16, %2;"
                             :: "r"(st_dst[k] + boff + STG_LO),
                                "l"(src + GP_HALF + st_moff[k]), "r"(st_sz[k]));
            }
            asm volatile("cp.async.commit_group;");
        }
        if (pre) { asm volatile("cp.async.wait_group 1;"); }
        else     { asm volatile("cp.async.wait_group 0;"); }
        __syncthreads();   // phase p data visible to all warps

        const uint32_t abuf = (uint32_t)(p & 1) * STG_BUF;
        const int tapbase = ph_tap[p];
        #pragma unroll
        for (int t9 = 0; t9 < 9; t9++) {
            const int s16 = ((t9 / 3 - 1) * PW + (t9 % 3 - 1)) * 16;
            const uint2 bf = sBF[(tapbase + t9) * 32 + lane];
            #pragma unroll
            for (int t = 0; t < 4; t++) {
                uint32_t r0, r1, r2, r3;
                ldm4(r0, r1, r2, r3, abase[t] + abuf + s16);
                // (r0,r1)=xhi rows, (r2,r3)=xlo rows
                mma16816(acc[t], r0, r1, r0, r1, bf.x, bf.y);   // xhi*(Whi+Wlo)
                mma1688 (acc[t], r2, r3, bf.x);                 // xlo*Whi
            }
        }
        __syncthreads();   // all warps done reading buf p&1 before it is rewritten
    }

    // epilogue
    const int oc0 = (lane & 3) * 2;
    const float bi0 = __ldg(&bias[oc0]);
    const float bi1 = __ldg(&bias[oc0 + 1]);
    const size_t obase0 = ((size_t)(b * 8 + oc0) * 49 + uv) * PLANE;
    #pragma unroll
    for (int t = 0; t < 4; t++) {
        const int mrow = R0 + wid * 64 + t * 16 + (lane >> 2);
        #pragma unroll
        for (int half = 0; half < 2; half++) {
            const int m = mrow + half * 8;
            const int hp = m / PW, wp = m - hp * PW;
            if (m < NPIX && hp >= 1 && hp <= 48 && wp >= 1 && wp <= 48) {
                const size_t o = obase0 + (hp - 1) * 48 + (wp - 1);
                out[o]                  = acc[t][half * 2]     + bi0;
                out[o + (size_t)CH_STR] = acc[t][half * 2 + 1] + bi1;
            }
        }
    }
}

extern "C" void kernel_launch(void* const* d_in, const int* in_sizes, int n_in,
                              void* d_out, int out_size)
{
    const float* x    = (const float*)d_in[0];
    const float* conv = (const float*)d_in[1];
    const float* bias = (const float*)d_in[2];
    float* out        = (float*)d_out;

    conv4d_prep<<<(2 * 49 * NPIX + 255) / 256, 256>>>(x);
    dim3 grid(10, 49, 2);   // 980 blocks
    conv4d_mma<<<grid, NTHREADS>>>(conv, bias, out);
}